// round 1
// baseline (speedup 1.0000x reference)
#include <cuda_runtime.h>
#include <cstdint>

// Problem constants
#define NB 8
#define NC 19
#define NH 512
#define NW 512
#define HW (NH * NW)          // 262144 = 2^18
#define NPIX (NB * HW)        // 2097152

// Accumulator layout in g_acc:
//   [0..18]  denom_c  = sum_pixels probs_c + count_c
//   [19..37] inter_c  = sum_{pixels with target c} p_t
//   [38] focal_sum   [39] nll_sum   [40] slp_sum (sum of per-pixel sum_c lp_c)
//   [41] bnll_sum (sum of nll * bmap)
#define NACC 42

__device__ float g_acc[NACC];
__device__ unsigned char g_diff[HW];
__device__ unsigned char g_bmap[HW];

// ---------------------------------------------------------------------------
__global__ void zero_kernel() {
    int i = threadIdx.x;
    if (i < NACC) g_acc[i] = 0.0f;
}

// diff[h][w] = any_b( targets[b, h-1..h+1, w] not all equal ),  h in [1,510]
__global__ void diff_kernel(const int* __restrict__ tgt) {
    int idx = blockIdx.x * blockDim.x + threadIdx.x;
    if (idx >= HW) return;
    int h = idx >> 9;
    int w = idx & (NW - 1);
    unsigned char d = 0;
    if (h >= 1 && h <= NH - 2) {
#pragma unroll
        for (int b = 0; b < NB; b++) {
            int base = b * HW + h * NW + w;
            int a = tgt[base - NW];
            int m = tgt[base];
            int q = tgt[base + NW];
            if ((a != m) | (a != q)) { d = 1; }
        }
    }
    g_diff[idx] = d;
}

// bmap[h][w] = interior ? diff[h][w-1] | diff[h][w] | diff[h][w+1] : 0
__global__ void bmap_kernel() {
    int idx = blockIdx.x * blockDim.x + threadIdx.x;
    if (idx >= HW) return;
    int h = idx >> 9;
    int w = idx & (NW - 1);
    unsigned char v = 0;
    if (h >= 1 && h <= NH - 2 && w >= 1 && w <= NW - 2) {
        v = g_diff[idx - 1] | g_diff[idx] | g_diff[idx + 1];
    }
    g_bmap[idx] = v;
}

// ---------------------------------------------------------------------------
__device__ __forceinline__ float warp_sum(float v) {
#pragma unroll
    for (int o = 16; o; o >>= 1) v += __shfl_down_sync(0xffffffffu, v, o);
    return v;
}

__global__ __launch_bounds__(256) void main_kernel(const float* __restrict__ in,
                                                   const int* __restrict__ tgt) {
    const int tid = blockIdx.x * blockDim.x + threadIdx.x;
    const int stride = gridDim.x * blockDim.x;

    float denom[NC];
    float inter[NC];
#pragma unroll
    for (int c = 0; c < NC; c++) { denom[c] = 0.0f; inter[c] = 0.0f; }
    float a_focal = 0.0f, a_nll = 0.0f, a_slp = 0.0f, a_bnll = 0.0f;

    for (int p = tid; p < NPIX; p += stride) {
        const int b = p >> 18;            // / HW
        const int hw = p & (HW - 1);
        const int t = tgt[p];
        const float* base = in + (size_t)b * (NC * HW) + hw;

        // pass 1: load channel values (no max subtraction: inputs ~ N(0,1))
        float x[NC];
        float sumx = 0.0f, xt = 0.0f;
#pragma unroll
        for (int c = 0; c < NC; c++) {
            x[c] = base[(size_t)c * HW];
            sumx += x[c];
            xt = (c == t) ? x[c] : xt;
        }

        // pass 2: exponentials + partition function
        float Z = 0.0f;
#pragma unroll
        for (int c = 0; c < NC; c++) {
            float e = __expf(x[c]);
            Z += e;
            x[c] = e;
        }
        const float invZ = __fdividef(1.0f, Z);
        const float logZ = __logf(Z);
        const float nll  = logZ - xt;     // -log p_t

        // pass 3: per-class probs -> dice accumulators (all in registers)
        float pt = 0.0f;
#pragma unroll
        for (int c = 0; c < NC; c++) {
            float pr = x[c] * invZ;
            float isT = (c == t) ? 1.0f : 0.0f;
            denom[c] += pr + isT;                 // sum probs + count, fused
            inter[c] = fmaf(isT, pr, inter[c]);   // p_t into its class
            pt = (c == t) ? pr : pt;
        }

        float om = 1.0f - pt;
        a_focal += om * om * nll;
        a_nll   += nll;
        a_slp   += sumx - (float)NC * logZ;       // sum_c lp_c for this pixel
        a_bnll  += nll * (float)g_bmap[hw];
    }

    // --- reduction: warp shuffle -> shared atomics -> global atomics ---
    __shared__ float s_acc[NACC];
    if (threadIdx.x < NACC) s_acc[threadIdx.x] = 0.0f;
    __syncthreads();

    const int lane = threadIdx.x & 31;

#pragma unroll
    for (int c = 0; c < NC; c++) {
        float v = warp_sum(denom[c]);
        if (lane == 0) atomicAdd(&s_acc[c], v);
    }
#pragma unroll
    for (int c = 0; c < NC; c++) {
        float v = warp_sum(inter[c]);
        if (lane == 0) atomicAdd(&s_acc[NC + c], v);
    }
    {
        float v = warp_sum(a_focal);
        if (lane == 0) atomicAdd(&s_acc[38], v);
        v = warp_sum(a_nll);
        if (lane == 0) atomicAdd(&s_acc[39], v);
        v = warp_sum(a_slp);
        if (lane == 0) atomicAdd(&s_acc[40], v);
        v = warp_sum(a_bnll);
        if (lane == 0) atomicAdd(&s_acc[41], v);
    }
    __syncthreads();
    if (threadIdx.x < NACC) atomicAdd(&g_acc[threadIdx.x], s_acc[threadIdx.x]);
}

// ---------------------------------------------------------------------------
__global__ void finalize_kernel(float* __restrict__ out) {
    if (threadIdx.x != 0 || blockIdx.x != 0) return;
    const double N = (double)NPIX;

    double focal = (double)g_acc[38] / N;

    double dice = 0.0;
#pragma unroll
    for (int c = 0; c < NC; c++) {
        double I = (double)g_acc[NC + c];
        double D = (double)g_acc[c];
        dice += 1.0 - (2.0 * I + 1e-5) / (D + 1e-5);
    }
    dice /= (double)NC;

    double nll_sum = (double)g_acc[39];
    double slp_sum = (double)g_acc[40];
    double ce = (0.9 * nll_sum + 0.1 * (-slp_sum) / (double)NC) / N;

    double boundary = (nll_sum + 0.5 * (double)g_acc[41]) / N;

    double total = focal + dice + ce + boundary;

    out[0] = (float)focal;
    out[1] = (float)dice;
    out[2] = (float)ce;
    out[3] = (float)boundary;
    out[4] = (float)total;
}

// ---------------------------------------------------------------------------
extern "C" void kernel_launch(void* const* d_in, const int* in_sizes, int n_in,
                              void* d_out, int out_size) {
    const float* inputs = (const float*)d_in[0];
    const int* targets = (const int*)d_in[1];
    float* out = (float*)d_out;

    zero_kernel<<<1, 64>>>();
    diff_kernel<<<HW / 512, 512>>>(targets);
    bmap_kernel<<<HW / 512, 512>>>();
    main_kernel<<<1024, 256>>>(inputs, targets);
    finalize_kernel<<<1, 32>>>(out);
}

// round 2
// speedup vs baseline: 1.2849x; 1.2849x over previous
#include <cuda_runtime.h>
#include <cstdint>

#define NB 8
#define NC 19
#define NH 512
#define NW 512
#define HW (NH * NW)            // 262144 = 2^18
#define NPIX (NB * HW)          // 2097152
#define NTHREADS 262144         // 1024 blocks * 256
#define NITER (NPIX / NTHREADS) // 8

// g_acc layout:
//  [0..18]  sum_pr_c (sum of probs per class)
//  [19..37] inter_c  (sum of p_t per target class)
//  [38] focal_sum  [39] nll_sum  [40] slp_sum  [41] bnll_sum
//  [42..60] count_c (target histogram)
#define NACC 61

__device__ float g_acc[NACC];
__device__ unsigned char g_diff[HW];
__device__ unsigned char g_bmap[HW];

// ---------------------------------------------------------------------------
// diff[h][w] = any_b( rows h-1..h+1 at col w not all equal ); also zeroes g_acc
__global__ void diff_kernel(const int* __restrict__ tgt) {
    int idx = blockIdx.x * blockDim.x + threadIdx.x;
    if (blockIdx.x == 0 && threadIdx.x < NACC) g_acc[threadIdx.x] = 0.0f;
    if (idx >= HW) return;
    int h = idx >> 9;
    unsigned char d = 0;
    if (h >= 1 && h <= NH - 2) {
#pragma unroll
        for (int b = 0; b < NB; b++) {
            int base = b * HW + idx;
            int a = tgt[base - NW];
            int m = tgt[base];
            int q = tgt[base + NW];
            d |= (unsigned char)((a != m) | (a != q));
        }
    }
    g_diff[idx] = d;
}

__global__ void bmap_kernel() {
    int idx = blockIdx.x * blockDim.x + threadIdx.x;
    if (idx >= HW) return;
    int h = idx >> 9;
    int w = idx & (NW - 1);
    unsigned char v = 0;
    if (h >= 1 && h <= NH - 2 && w >= 1 && w <= NW - 2) {
        v = g_diff[idx - 1] | g_diff[idx] | g_diff[idx + 1];
    }
    g_bmap[idx] = v;
}

// ---------------------------------------------------------------------------
__device__ __forceinline__ float warp_sum(float v) {
#pragma unroll
    for (int o = 16; o; o >>= 1) v += __shfl_down_sync(0xffffffffu, v, o);
    return v;
}

__global__ __launch_bounds__(256) void main_kernel(const float* __restrict__ in,
                                                   const int* __restrict__ tgt) {
    __shared__ float s_blk[NACC];
    if (threadIdx.x < NACC) s_blk[threadIdx.x] = 0.0f;
    __syncthreads();

    const int tid = blockIdx.x * 256 + threadIdx.x;
    const int hw = tid;                       // since NTHREADS == HW
    const float bm = (float)g_bmap[hw];       // loop-invariant boundary flag

    float denom[NC];
#pragma unroll
    for (int c = 0; c < NC; c++) denom[c] = 0.0f;
    float a_focal = 0.0f, a_nll = 0.0f, a_slp = 0.0f, a_bnll = 0.0f;

#pragma unroll 1
    for (int b = 0; b < NITER; b++) {
        const int t = tgt[b * HW + hw];
        const float* base = in + (size_t)b * (NC * HW) + hw;

        // 19 independent coalesced loads (front-batched -> high MLP)
        float x[NC];
#pragma unroll
        for (int c = 0; c < NC; c++) x[c] = __ldg(base + (size_t)c * HW);
        // gather of the target logit: guaranteed L1 hit (lines just loaded)
        const float xt = __ldg(base + (size_t)t * HW);

        // sum of logits (4 independent chains)
        float s0 = 0.f, s1 = 0.f, s2 = 0.f, s3 = 0.f;
#pragma unroll
        for (int c = 0; c < NC; c++) {
            if ((c & 3) == 0) s0 += x[c];
            else if ((c & 3) == 1) s1 += x[c];
            else if ((c & 3) == 2) s2 += x[c];
            else s3 += x[c];
        }
        const float sumx = (s0 + s1) + (s2 + s3);

        // exponentials in place + partition function (4 chains)
        float z0 = 0.f, z1 = 0.f, z2 = 0.f, z3 = 0.f;
#pragma unroll
        for (int c = 0; c < NC; c++) {
            x[c] = __expf(x[c]);
            if ((c & 3) == 0) z0 += x[c];
            else if ((c & 3) == 1) z1 += x[c];
            else if ((c & 3) == 2) z2 += x[c];
            else z3 += x[c];
        }
        const float Z = (z0 + z1) + (z2 + z3);

        const float invZ = __fdividef(1.0f, Z);
        const float logZ = __logf(Z);
        const float nll = logZ - xt;
        const float pt = __expf(xt) * invZ;

        // per-class prob sums: one FFMA per class, no predicates
#pragma unroll
        for (int c = 0; c < NC; c++) denom[c] = fmaf(x[c], invZ, denom[c]);

        const float om = 1.0f - pt;
        a_focal = fmaf(om * om, nll, a_focal);
        a_nll += nll;
        a_slp += fmaf(-(float)NC, logZ, sumx);
        a_bnll = fmaf(nll, bm, a_bnll);

        // one-hot accumulators via shared atomics (replaces 19-wide sel chains)
        atomicAdd(&s_blk[NC + t], pt);        // inter
        atomicAdd(&s_blk[42 + t], 1.0f);      // count
    }

    // --- block reduction: warp shuffle -> shared atomics ---
    const int lane = threadIdx.x & 31;
#pragma unroll
    for (int c = 0; c < NC; c++) {
        float v = warp_sum(denom[c]);
        if (lane == 0) atomicAdd(&s_blk[c], v);
    }
    {
        float v = warp_sum(a_focal);
        if (lane == 0) atomicAdd(&s_blk[38], v);
        v = warp_sum(a_nll);
        if (lane == 0) atomicAdd(&s_blk[39], v);
        v = warp_sum(a_slp);
        if (lane == 0) atomicAdd(&s_blk[40], v);
        v = warp_sum(a_bnll);
        if (lane == 0) atomicAdd(&s_blk[41], v);
    }
    __syncthreads();
    if (threadIdx.x < NACC) atomicAdd(&g_acc[threadIdx.x], s_blk[threadIdx.x]);
}

// ---------------------------------------------------------------------------
__global__ void finalize_kernel(float* __restrict__ out) {
    if (threadIdx.x != 0 || blockIdx.x != 0) return;
    const double N = (double)NPIX;

    double focal = (double)g_acc[38] / N;

    double dice = 0.0;
#pragma unroll
    for (int c = 0; c < NC; c++) {
        double I = (double)g_acc[NC + c];
        double D = (double)g_acc[c] + (double)g_acc[42 + c];
        dice += 1.0 - (2.0 * I + 1e-5) / (D + 1e-5);
    }
    dice /= (double)NC;

    double nll_sum = (double)g_acc[39];
    double slp_sum = (double)g_acc[40];
    double ce = (0.9 * nll_sum + 0.1 * (-slp_sum) / (double)NC) / N;

    double boundary = (nll_sum + 0.5 * (double)g_acc[41]) / N;

    double total = focal + dice + ce + boundary;

    out[0] = (float)focal;
    out[1] = (float)dice;
    out[2] = (float)ce;
    out[3] = (float)boundary;
    out[4] = (float)total;
}

// ---------------------------------------------------------------------------
extern "C" void kernel_launch(void* const* d_in, const int* in_sizes, int n_in,
                              void* d_out, int out_size) {
    const float* inputs = (const float*)d_in[0];
    const int* targets = (const int*)d_in[1];
    float* out = (float*)d_out;

    diff_kernel<<<HW / 512, 512>>>(targets);
    bmap_kernel<<<HW / 512, 512>>>();
    main_kernel<<<1024, 256>>>(inputs, targets);
    finalize_kernel<<<1, 32>>>(out);
}

// round 3
// speedup vs baseline: 1.3499x; 1.0506x over previous
#include <cuda_runtime.h>
#include <cstdint>

#define NB 8
#define NC 19
#define NH 512
#define NW 512
#define HW (NH * NW)            // 262144 = 2^18
#define NPIX (NB * HW)          // 2097152
#define NITER 8                 // batches per thread (NTHREADS == HW)

// g_acc layout:
//  [0..18]  denom_c = sum probs_c + count_c
//  [19..37] inter_c = sum of p_t for pixels with target c
//  [38] focal_sum  [39] nll_sum  [40] slp_sum  [41] bnll_sum
#define NACC 42

__device__ float g_acc[NACC];
__device__ unsigned char g_diff[HW];

// ---------------------------------------------------------------------------
// diff[h][w] = any_b( rows h-1..h+1 at col w not all equal ); also zeroes g_acc
__global__ void diff_kernel(const int* __restrict__ tgt) {
    int idx = blockIdx.x * blockDim.x + threadIdx.x;
    if (blockIdx.x == 0 && threadIdx.x < NACC) g_acc[threadIdx.x] = 0.0f;
    if (idx >= HW) return;
    int h = idx >> 9;
    unsigned char d = 0;
    if (h >= 1 && h <= NH - 2) {
#pragma unroll
        for (int b = 0; b < NB; b++) {
            int base = b * HW + idx;
            int a = tgt[base - NW];
            int m = tgt[base];
            int q = tgt[base + NW];
            d |= (unsigned char)((a != m) | (a != q));
        }
    }
    g_diff[idx] = d;
}

// ---------------------------------------------------------------------------
__device__ __forceinline__ float warp_sum(float v) {
#pragma unroll
    for (int o = 16; o; o >>= 1) v += __shfl_down_sync(0xffffffffu, v, o);
    return v;
}

__global__ __launch_bounds__(256, 3) void main_kernel(const float* __restrict__ in,
                                                      const int* __restrict__ tgt) {
    __shared__ float s_blk[NACC];
    if (threadIdx.x < NACC) s_blk[threadIdx.x] = 0.0f;
    __syncthreads();

    const int hw = blockIdx.x * 256 + threadIdx.x;   // NTHREADS == HW
    const int h = hw >> 9;
    const int w = hw & (NW - 1);

    // boundary flag: OR of the 3 neighbor-column diffs (interior only)
    float bm = 0.0f;
    if (h >= 1 && h <= NH - 2 && w >= 1 && w <= NW - 2) {
        bm = (float)(g_diff[hw - 1] | g_diff[hw] | g_diff[hw + 1]);
    }

    float denom[NC];
    float inter[NC];
#pragma unroll
    for (int c = 0; c < NC; c++) { denom[c] = 0.0f; inter[c] = 0.0f; }
    float a_focal = 0.0f, a_nll = 0.0f, a_slp = 0.0f, a_bnll = 0.0f;

#pragma unroll 1
    for (int b = 0; b < NITER; b++) {
        const int t = tgt[b * HW + hw];
        const float* base = in + (size_t)b * (NC * HW) + hw;

        // 19 independent coalesced loads (front-batched -> high MLP)
        float x[NC];
#pragma unroll
        for (int c = 0; c < NC; c++) x[c] = __ldg(base + (size_t)c * HW);
        // target logit gather: same cache lines just loaded -> L1 hit
        const float xt = __ldg(base + (size_t)t * HW);

        // sum of logits, 4 independent chains
        float s0 = 0.f, s1 = 0.f, s2 = 0.f, s3 = 0.f;
#pragma unroll
        for (int c = 0; c < NC; c++) {
            if ((c & 3) == 0) s0 += x[c];
            else if ((c & 3) == 1) s1 += x[c];
            else if ((c & 3) == 2) s2 += x[c];
            else s3 += x[c];
        }
        const float sumx = (s0 + s1) + (s2 + s3);

        // exponentials + partition function, 4 chains
        float z0 = 0.f, z1 = 0.f, z2 = 0.f, z3 = 0.f;
#pragma unroll
        for (int c = 0; c < NC; c++) {
            x[c] = __expf(x[c]);
            if ((c & 3) == 0) z0 += x[c];
            else if ((c & 3) == 1) z1 += x[c];
            else if ((c & 3) == 2) z2 += x[c];
            else z3 += x[c];
        }
        const float Z = (z0 + z1) + (z2 + z3);

        const float invZ = __fdividef(1.0f, Z);
        const float logZ = __logf(Z);
        const float nll = logZ - xt;
        const float pt = __expf(xt) * invZ;

        // per-class accumulators: 1 FFMA + 1 ISETP + 2 predicated FADD, no LSU
#pragma unroll
        for (int c = 0; c < NC; c++) {
            denom[c] = fmaf(x[c], invZ, denom[c]);
            if (c == t) {
                denom[c] += 1.0f;     // one-hot count folded into denominator
                inter[c] += pt;       // intersection term
            }
        }

        const float om = 1.0f - pt;
        a_focal = fmaf(om * om, nll, a_focal);
        a_nll += nll;
        a_slp += fmaf(-(float)NC, logZ, sumx);
        a_bnll = fmaf(nll, bm, a_bnll);
    }

    // --- block reduction: warp shuffle -> shared atomics -> global atomics ---
    const int lane = threadIdx.x & 31;
#pragma unroll
    for (int c = 0; c < NC; c++) {
        float v = warp_sum(denom[c]);
        if (lane == 0) atomicAdd(&s_blk[c], v);
    }
#pragma unroll
    for (int c = 0; c < NC; c++) {
        float v = warp_sum(inter[c]);
        if (lane == 0) atomicAdd(&s_blk[NC + c], v);
    }
    {
        float v = warp_sum(a_focal);
        if (lane == 0) atomicAdd(&s_blk[38], v);
        v = warp_sum(a_nll);
        if (lane == 0) atomicAdd(&s_blk[39], v);
        v = warp_sum(a_slp);
        if (lane == 0) atomicAdd(&s_blk[40], v);
        v = warp_sum(a_bnll);
        if (lane == 0) atomicAdd(&s_blk[41], v);
    }
    __syncthreads();
    if (threadIdx.x < NACC) atomicAdd(&g_acc[threadIdx.x], s_blk[threadIdx.x]);
}

// ---------------------------------------------------------------------------
// Warp-parallel finalize, float math throughout (rel-err budget 1e-3).
__global__ void finalize_kernel(float* __restrict__ out) {
    const int lane = threadIdx.x;
    const float Ninv = 1.0f / (float)NPIX;

    // parallel loads of the accumulators
    float denom = (lane < NC) ? g_acc[lane] : 0.0f;
    float inter = (lane < NC) ? g_acc[NC + lane] : 0.0f;

    // per-class dice term on lanes 0..18, then warp-reduce
    float d = 0.0f;
    if (lane < NC) d = 1.0f - (2.0f * inter + 1e-5f) / (denom + 1e-5f);
    d = warp_sum(d);

    if (lane == 0) {
        float dice = d / (float)NC;
        float focal = g_acc[38] * Ninv;
        float nll_sum = g_acc[39];
        float slp_sum = g_acc[40];
        float ce = (0.9f * nll_sum - 0.1f * slp_sum / (float)NC) * Ninv;
        float boundary = (nll_sum + 0.5f * g_acc[41]) * Ninv;
        float total = focal + dice + ce + boundary;
        out[0] = focal;
        out[1] = dice;
        out[2] = ce;
        out[3] = boundary;
        out[4] = total;
    }
}

// ---------------------------------------------------------------------------
extern "C" void kernel_launch(void* const* d_in, const int* in_sizes, int n_in,
                              void* d_out, int out_size) {
    const float* inputs = (const float*)d_in[0];
    const int* targets = (const int*)d_in[1];
    float* out = (float*)d_out;

    diff_kernel<<<HW / 512, 512>>>(targets);
    main_kernel<<<HW / 256, 256>>>(inputs, targets);
    finalize_kernel<<<1, 32>>>(out);
}